// round 7
// baseline (speedup 1.0000x reference)
#include <cuda_runtime.h>
#include <cstdint>

static constexpr int NTOK = 32768;   // 8 * 4096
static constexpr int DIM  = 512;
static constexpr int HID  = 2048;
static constexpr int NEXP = 8;
static constexpr int MAXE = 2 * NTOK;

// GEMM tiling
static constexpr int BM = 128, BN = 256, BK = 32;
static constexpr int STRIDE = 36;                        // floats per smem row (16B aligned, conflict-free frags)
static constexpr int A_FLOATS = BM * STRIDE;             // 4608
static constexpr int B_FLOATS = BN * STRIDE;             // 9216
static constexpr int STAGE_FLOATS = A_FLOATS + B_FLOATS; // 13824
static constexpr int STAGES = 3;
static constexpr int SMEM_BYTES = STAGES * STAGE_FLOATS * 4;  // 165888

// ---------------- scratch ----------------
__device__ int   g_counts[NEXP];
__device__ int   g_offsets[NEXP + 1];
__device__ int   g_cursors[NEXP];
__device__ int   g_tok[MAXE];
__device__ float g_w[MAXE];
__device__ int   g_cnt[NTOK];
__device__ int   g_pos[2 * NTOK];
// g_xy: doubles as packed x (first NTOK*DIM floats, live until end of GEMM1)
// and as per-entry output y (MAXE*DIM floats, written by GEMM2, read by gather).
__device__ float g_xy[(long long)MAXE * DIM];          // 128 MB
__device__ float g_W1p[(long long)NEXP * HID * DIM];   // [e][n][k-packed] 32 MB
__device__ float g_W2p[(long long)NEXP * DIM * HID];   // [e][n][k-packed] 32 MB
__device__ float g_h[(long long)MAXE * HID];           // packed hidden, 512 MB

// ---------------- helpers ----------------
__device__ __forceinline__ uint32_t smem_u32(const void* p) {
    uint32_t a;
    asm("{ .reg .u64 t; cvta.to.shared.u64 t, %1; cvt.u32.u64 %0, t; }" : "=r"(a) : "l"(p));
    return a;
}
__device__ __forceinline__ void cp16(uint32_t daddr, const void* gptr) {
    asm volatile("cp.async.cg.shared.global [%0], [%1], 16;" :: "r"(daddr), "l"(gptr) : "memory");
}
__device__ __forceinline__ uint32_t to_tf32(float f) {
    uint32_t u;
    asm("cvt.rna.tf32.f32 %0, %1;" : "=r"(u) : "f"(f));
    return u;
}
__device__ __forceinline__ float round_tf32(float f) { return __uint_as_float(to_tf32(f)); }

__device__ __forceinline__ void mma1688(float* c, uint32_t a0, uint32_t a1, uint32_t a2, uint32_t a3,
                                        uint32_t b0, uint32_t b1) {
    asm volatile(
        "mma.sync.aligned.m16n8k8.row.col.f32.tf32.tf32.f32 "
        "{%0,%1,%2,%3}, {%4,%5,%6,%7}, {%8,%9}, {%0,%1,%2,%3};"
        : "+f"(c[0]), "+f"(c[1]), "+f"(c[2]), "+f"(c[3])
        : "r"(a0), "r"(a1), "r"(a2), "r"(a3), "r"(b0), "r"(b1));
}

// packed k position: within each 32-k block, pos(k) = (k%4)*8 + (k%32)/4
__device__ __forceinline__ int pk(int k) {
    return (k & ~31) + (k & 3) * 8 + ((k & 31) >> 2);
}

// ---------------- routing ----------------
__global__ void k_zero() {
    if (threadIdx.x < NEXP) g_counts[threadIdx.x] = 0;
}
__global__ void k_count(const int* __restrict__ assign) {
    int t = blockIdx.x * blockDim.x + threadIdx.x;
    if (t >= NTOK) return;
    int a0 = assign[2 * t], a1 = assign[2 * t + 1];
    atomicAdd(&g_counts[a0], 1);
    if (a1 != a0) atomicAdd(&g_counts[a1], 1);
}
__global__ void k_scan() {
    int off = 0;
    for (int e = 0; e < NEXP; e++) {
        g_offsets[e] = off;
        g_cursors[e] = off;
        off += g_counts[e];
    }
    g_offsets[NEXP] = off;
}
__global__ void k_place(const int* __restrict__ assign) {
    int t = blockIdx.x * blockDim.x + threadIdx.x;
    if (t >= NTOK) return;
    int a0 = assign[2 * t], a1 = assign[2 * t + 1];
    if (a0 == a1) {
        int p = atomicAdd(&g_cursors[a0], 1);
        g_tok[p] = t; g_w[p] = 1.0f;
        g_pos[2 * t] = p; g_cnt[t] = 1;
    } else {
        int p = atomicAdd(&g_cursors[a0], 1);
        g_tok[p] = t; g_w[p] = 0.5f;
        int q = atomicAdd(&g_cursors[a1], 1);
        g_tok[q] = t; g_w[q] = 0.5f;
        g_pos[2 * t] = p; g_pos[2 * t + 1] = q; g_cnt[t] = 2;
    }
}

// ---------------- pre-pack: x -> tf32-rounded, k-packed (into g_xy) ----------------
__global__ void k_pack_x(const float* __restrict__ x) {
    int t = blockIdx.x;
    int k = threadIdx.x * 4;           // 128 threads * 4 = 512
    float4 v = *(const float4*)(x + (long long)t * DIM + k);
    float* dst = g_xy + (long long)t * DIM;
    dst[pk(k + 0)] = round_tf32(v.x);
    dst[pk(k + 1)] = round_tf32(v.y);
    dst[pk(k + 2)] = round_tf32(v.z);
    dst[pk(k + 3)] = round_tf32(v.w);
}

// ---------------- pre-pack: W [e][K][N] -> [e][n][k-packed], tf32-rounded ----------------
template <bool W1SEL>
__global__ void k_pack_w(const float* __restrict__ src, int K, int N) {
    __shared__ float tile[32][33];
    float* dst = W1SEL ? g_W1p : g_W2p;
    long long eoff = (long long)blockIdx.z * K * N;
    int n0 = blockIdx.x * 32, k0 = blockIdx.y * 32;
    #pragma unroll
    for (int i = threadIdx.y; i < 32; i += 8)
        tile[i][threadIdx.x] = src[eoff + (long long)(k0 + i) * N + n0 + threadIdx.x];
    __syncthreads();
    int tx = threadIdx.x;
    int pkx = k0 + (tx & 3) * 8 + (tx >> 2);      // pk(k0+tx), k0 % 32 == 0
    #pragma unroll
    for (int i = threadIdx.y; i < 32; i += 8)
        dst[eoff + (long long)(n0 + i) * K + pkx] = round_tf32(tile[tx][i]);
}

// ---------------- tf32 mma.sync GEMM, packed fragments ----------------
// Block 128x256x32, 8 warps (2m x 4n), warp tile 64x64.
// G1: g_h(packed) = relu(xp[g_tok] @ W1p + b1)    KTOT=512,  NTOT=2048
// G2: g_xy(=y) = (g_h @ W2p + b2) * g_w           KTOT=2048, NTOT=512
template <int KTOT, bool G1>
__global__ void __launch_bounds__(256) k_gemm(const float* __restrict__ bias)
{
    constexpr int NTOT = G1 ? HID : DIM;
    constexpr int CH = KTOT / BK;

    extern __shared__ float sm[];

    int e = blockIdx.z;
    int seg0 = g_offsets[e], seg1 = g_offsets[e + 1];
    int m0 = seg0 + blockIdx.y * BM;
    if (m0 >= seg1) return;
    int n0 = blockIdx.x * BN;

    const float* Asrc = G1 ? (const float*)g_xy : (const float*)g_h;
    const float* W    = G1 ? (const float*)g_W1p : (const float*)g_W2p;

    int tid = threadIdx.x;
    int lane = tid & 31, wid = tid >> 5;
    int warp_m = wid & 1, warp_n = wid >> 1;

    // ---- cp.async mapping ----
    int ar_ld = tid >> 1;                       // A row 0..127
    int ahalf = (tid & 1) * 16;                 // 16-float half
    int gmr = min(m0 + ar_ld, seg1 - 1);
    long long srow = G1 ? (long long)g_tok[gmr] : (long long)gmr;
    const float* aSrc = Asrc + srow * KTOT + ahalf;
    uint32_t aDst = smem_u32(sm) + (uint32_t)(ar_ld * STRIDE + ahalf) * 4u;

    const float* bSrc = W + ((long long)e * NTOT + (n0 + tid)) * (long long)KTOT;
    uint32_t bDst = smem_u32(sm) + (uint32_t)(A_FLOATS + tid * STRIDE) * 4u;

    auto load_chunk = [&](int c, int s) {
        uint32_t so = (uint32_t)(s * STAGE_FLOATS) * 4u;
        const float* a = aSrc + c * BK;
        #pragma unroll
        for (int i = 0; i < 4; i++) cp16(aDst + so + i * 16, a + i * 4);
        const float* b = bSrc + c * BK;
        #pragma unroll
        for (int i = 0; i < 8; i++) cp16(bDst + so + i * 16, b + i * 4);
        asm volatile("cp.async.commit_group;" ::: "memory");
    };

    float acc[4][8][4];
    #pragma unroll
    for (int mi = 0; mi < 4; mi++)
        #pragma unroll
        for (int nj = 0; nj < 8; nj++)
            #pragma unroll
            for (int q = 0; q < 4; q++) acc[mi][nj][q] = 0.0f;

    load_chunk(0, 0);
    load_chunk(1, 1);

    // fragment base offsets (in floats) within a stage
    int afrag = (warp_m * 64 + (lane >> 2)) * STRIDE + (lane & 3) * 8;
    int bfrag = A_FLOATS + (warp_n * 64 + (lane >> 2)) * STRIDE + (lane & 3) * 8;

    for (int c = 0; c < CH; c++) {
        int s = c % STAGES;
        if (c + 1 < CH) asm volatile("cp.async.wait_group 1;" ::: "memory");
        else            asm volatile("cp.async.wait_group 0;" ::: "memory");
        __syncthreads();

        const uint32_t* st = (const uint32_t*)(sm + s * STAGE_FLOATS);

        #pragma unroll
        for (int half = 0; half < 2; half++) {
            // A: 8 row-groups (mi x {r, r+8}), one v4 each — keep these live
            uint4 aR[8];
            #pragma unroll
            for (int mi = 0; mi < 4; mi++) {
                aR[mi * 2 + 0] = *(const uint4*)(st + afrag + (mi * 16 + 0) * STRIDE + half * 4);
                aR[mi * 2 + 1] = *(const uint4*)(st + afrag + (mi * 16 + 8) * STRIDE + half * 4);
            }
            // B: stream one v4 at a time to bound register pressure
            #pragma unroll
            for (int nj = 0; nj < 8; nj++) {
                uint4 b = *(const uint4*)(st + bfrag + nj * 8 * STRIDE + half * 4);
                #pragma unroll
                for (int mi = 0; mi < 4; mi++) {
                    mma1688(acc[mi][nj],
                            aR[mi * 2].x, aR[mi * 2 + 1].x, aR[mi * 2].y, aR[mi * 2 + 1].y,
                            b.x, b.y);
                    mma1688(acc[mi][nj],
                            aR[mi * 2].z, aR[mi * 2 + 1].z, aR[mi * 2].w, aR[mi * 2 + 1].w,
                            b.z, b.w);
                }
            }
        }

        __syncthreads();
        if (c + 2 < CH) load_chunk(c + 2, (c + 2) % STAGES);
    }

    // ---- epilogue ----
    const float* bias_e = bias + (long long)e * NTOT;
    float2 bv[8];
    #pragma unroll
    for (int nj = 0; nj < 8; nj++) {
        int col = n0 + warp_n * 64 + nj * 8 + (lane & 3) * 2;
        bv[nj] = *(const float2*)(bias_e + col);
    }

    #pragma unroll
    for (int mi = 0; mi < 4; mi++) {
        int r0 = m0 + warp_m * 64 + mi * 16 + (lane >> 2);
        int r1 = r0 + 8;
        bool ok0 = r0 < seg1, ok1 = r1 < seg1;
        if (G1) {
            float* d0 = g_h + (long long)r0 * HID;
            float* d1 = g_h + (long long)r1 * HID;
            #pragma unroll
            for (int nj = 0; nj < 8; nj++) {
                int col = n0 + warp_n * 64 + nj * 8 + (lane & 3) * 2;
                int c0 = pk(col), c1 = pk(col + 1);
                if (ok0) {
                    d0[c0] = round_tf32(fmaxf(acc[mi][nj][0] + bv[nj].x, 0.0f));
                    d0[c1] = round_tf32(fmaxf(acc[mi][nj][1] + bv[nj].y, 0.0f));
                }
                if (ok1) {
                    d1[c0] = round_tf32(fmaxf(acc[mi][nj][2] + bv[nj].x, 0.0f));
                    d1[c1] = round_tf32(fmaxf(acc[mi][nj][3] + bv[nj].y, 0.0f));
                }
            }
        } else {
            float w0 = ok0 ? g_w[r0] : 0.0f;
            float w1 = ok1 ? g_w[r1] : 0.0f;
            float* d0 = g_xy + (long long)r0 * DIM;
            float* d1 = g_xy + (long long)r1 * DIM;
            #pragma unroll
            for (int nj = 0; nj < 8; nj++) {
                int col = n0 + warp_n * 64 + nj * 8 + (lane & 3) * 2;
                float2 v0, v1;
                v0.x = (acc[mi][nj][0] + bv[nj].x) * w0;
                v0.y = (acc[mi][nj][1] + bv[nj].y) * w0;
                v1.x = (acc[mi][nj][2] + bv[nj].x) * w1;
                v1.y = (acc[mi][nj][3] + bv[nj].y) * w1;
                if (ok0) *(float2*)(d0 + col) = v0;
                if (ok1) *(float2*)(d1 + col) = v1;
            }
        }
    }
}

// ---------------- per-token gather (y lives in g_xy) ----------------
__global__ void k_gather(float* __restrict__ out) {
    int t = blockIdx.x;
    int c = threadIdx.x;   // 128 threads * float4 = 512 floats
    int cnt = g_cnt[t];
    int p0 = g_pos[2 * t];
    float4 v = ((const float4*)(g_xy + (long long)p0 * DIM))[c];
    if (cnt == 2) {
        int p1 = g_pos[2 * t + 1];
        float4 u = ((const float4*)(g_xy + (long long)p1 * DIM))[c];
        v.x += u.x; v.y += u.y; v.z += u.z; v.w += u.w;
    }
    ((float4*)(out + (long long)t * DIM))[c] = v;
}

// ---------------- launch ----------------
extern "C" void kernel_launch(void* const* d_in, const int* in_sizes, int n_in,
                              void* d_out, int out_size)
{
    const float* x      = (const float*)d_in[0];
    const int*   assign = (const int*)d_in[1];
    const float* W1     = (const float*)d_in[2];
    const float* b1     = (const float*)d_in[3];
    const float* W2     = (const float*)d_in[4];
    const float* b2     = (const float*)d_in[5];
    float* out = (float*)d_out;

    cudaFuncSetAttribute(k_gemm<DIM, true>,  cudaFuncAttributeMaxDynamicSharedMemorySize, SMEM_BYTES);
    cudaFuncSetAttribute(k_gemm<HID, false>, cudaFuncAttributeMaxDynamicSharedMemorySize, SMEM_BYTES);

    // pre-pack (round to tf32, k-fragment packing; W also transposed to [n][k])
    k_pack_x<<<NTOK, 128>>>(x);
    dim3 tb(32, 8);
    k_pack_w<true ><<<dim3(HID / 32, DIM / 32, NEXP), tb>>>(W1, DIM, HID);
    k_pack_w<false><<<dim3(DIM / 32, HID / 32, NEXP), tb>>>(W2, HID, DIM);

    // routing
    k_zero<<<1, 32>>>();
    k_count<<<NTOK / 256, 256>>>(assign);
    k_scan<<<1, 1>>>();
    k_place<<<NTOK / 256, 256>>>(assign);

    // GEMM1: entries x 512 @ 512 x 2048 -> g_h (packed)
    dim3 g1(HID / BN, MAXE / BM, NEXP);   // (8, 512, 8)
    k_gemm<DIM, true><<<g1, 256, SMEM_BYTES>>>(b1);

    // GEMM2: entries x 2048 @ 2048 x 512 -> g_xy (y)
    dim3 g2(DIM / BN, MAXE / BM, NEXP);   // (2, 512, 8)
    k_gemm<HID, false><<<g2, 256, SMEM_BYTES>>>(b2);

    k_gather<<<NTOK, 128>>>(out);
}

// round 8
// speedup vs baseline: 2.5200x; 2.5200x over previous
#include <cuda_runtime.h>
#include <cuda_fp16.h>
#include <cstdint>

static constexpr int NTOK = 32768;   // 8 * 4096
static constexpr int DIM  = 512;
static constexpr int HID  = 2048;
static constexpr int NEXP = 8;
static constexpr int MAXE = 2 * NTOK;

// GEMM tiling: block 128x256x32(halves), 8 warps (2m x 4n), warp tile 64x64, mma m16n8k16 f16
static constexpr int BM = 128, BN = 256, BKH = 32;       // BKH halves per chunk = 64 B/row
static constexpr int A_BYTES = BM * 64;                  // 8192
static constexpr int B_BYTES = BN * 64;                  // 16384
static constexpr int STAGE_BYTES = A_BYTES + B_BYTES;    // 24576
static constexpr int STAGES = 3;
static constexpr int SMEM_BYTES = STAGES * STAGE_BYTES;  // 73728 (also >= 128*132*4 epilogue stage)

// ---------------- scratch ----------------
__device__ int   g_counts[NEXP];
__device__ int   g_offsets[NEXP + 1];
__device__ int   g_cursors[NEXP];
__device__ int   g_tok[MAXE];
__device__ float g_w[MAXE];
__device__ int   g_cnt[NTOK];
__device__ int   g_pos[2 * NTOK];
__device__ __align__(16) __half g_xh[(long long)NTOK * DIM];         // 32 MB  packed fp16 x
__device__ __align__(16) __half g_W1h[(long long)NEXP * HID * DIM];  // 16 MB  [e][n][k-packed]
__device__ __align__(16) __half g_W2h[(long long)NEXP * DIM * HID];  // 16 MB  [e][n][k-packed]
__device__ __align__(16) __half g_h[(long long)MAXE * HID];          // 256 MB packed fp16 hidden
__device__ __align__(16) float  g_y[(long long)MAXE * DIM];          // 128 MB per-entry output

// ---------------- helpers ----------------
__device__ __forceinline__ uint32_t smem_u32(const void* p) {
    uint32_t a;
    asm("{ .reg .u64 t; cvta.to.shared.u64 t, %1; cvt.u32.u64 %0, t; }" : "=r"(a) : "l"(p));
    return a;
}
__device__ __forceinline__ void cp16(uint32_t daddr, const void* gptr) {
    asm volatile("cp.async.cg.shared.global [%0], [%1], 16;" :: "r"(daddr), "l"(gptr) : "memory");
}
__device__ __forceinline__ uint32_t h2u(__half2 h) { return *(uint32_t*)&h; }

__device__ __forceinline__ void mma16816(float* c, uint32_t a0, uint32_t a1, uint32_t a2, uint32_t a3,
                                         uint32_t b0, uint32_t b1) {
    asm volatile(
        "mma.sync.aligned.m16n8k16.row.col.f32.f16.f16.f32 "
        "{%0,%1,%2,%3}, {%4,%5,%6,%7}, {%8,%9}, {%0,%1,%2,%3};"
        : "+f"(c[0]), "+f"(c[1]), "+f"(c[2]), "+f"(c[3])
        : "r"(a0), "r"(a1), "r"(a2), "r"(a3), "r"(b0), "r"(b1));
}

// k-pack over 32-half groups: packed u32 p <- orig u32 o, with p = 4*(o%4) + o/4.
// Thread c then reads packed u32s [4c,4c+4) = orig {c, c+4, c+8, c+12}
//   = (blk0 lo, blk0 hi, blk1 lo, blk1 hi) fragments of mma m16n8k16.

// ---------------- routing ----------------
__global__ void k_zero() {
    if (threadIdx.x < NEXP) g_counts[threadIdx.x] = 0;
}
__global__ void k_count(const int* __restrict__ assign) {
    int t = blockIdx.x * blockDim.x + threadIdx.x;
    if (t >= NTOK) return;
    int a0 = assign[2 * t], a1 = assign[2 * t + 1];
    atomicAdd(&g_counts[a0], 1);
    if (a1 != a0) atomicAdd(&g_counts[a1], 1);
}
__global__ void k_scan() {
    int off = 0;
    for (int e = 0; e < NEXP; e++) {
        g_offsets[e] = off;
        g_cursors[e] = off;
        off += g_counts[e];
    }
    g_offsets[NEXP] = off;
}
__global__ void k_place(const int* __restrict__ assign) {
    int t = blockIdx.x * blockDim.x + threadIdx.x;
    if (t >= NTOK) return;
    int a0 = assign[2 * t], a1 = assign[2 * t + 1];
    if (a0 == a1) {
        int p = atomicAdd(&g_cursors[a0], 1);
        g_tok[p] = t; g_w[p] = 1.0f;
        g_pos[2 * t] = p; g_cnt[t] = 1;
    } else {
        int p = atomicAdd(&g_cursors[a0], 1);
        g_tok[p] = t; g_w[p] = 0.5f;
        int q = atomicAdd(&g_cursors[a1], 1);
        g_tok[q] = t; g_w[q] = 0.5f;
        g_pos[2 * t] = p; g_pos[2 * t + 1] = q; g_cnt[t] = 2;
    }
}

// ---------------- pre-pack: x fp32 -> fp16 k-packed ----------------
__global__ void k_pack_x(const float* __restrict__ x) {
    int t = blockIdx.x;
    int q = threadIdx.x;                 // output u32 index within row, 256 = DIM/2
    int group = q >> 4, p = q & 15;
    int o = (p & 3) * 4 + (p >> 2);      // inverse of p = 4*(o%4)+o/4
    int col = group * 32 + 2 * o;
    float2 v = *(const float2*)(x + (long long)t * DIM + col);
    ((uint32_t*)g_xh)[(long long)t * (DIM / 2) + q] = h2u(__floats2half2_rn(v.x, v.y));
}

// ---------------- pre-pack: W [e][K][N] -> [e][n][k-packed] fp16 ----------------
template <bool W1SEL>
__global__ void k_pack_w(const float* __restrict__ src, int K, int N) {
    __shared__ float tile[32][33];
    __half* dstb = W1SEL ? g_W1h : g_W2h;
    long long eoff = (long long)blockIdx.z * K * N;
    int n0 = blockIdx.x * 32, k0 = blockIdx.y * 32;
    int tx = threadIdx.x, ty = threadIdx.y;
    #pragma unroll
    for (int i = ty; i < 32; i += 8)
        tile[i][tx] = src[eoff + (long long)(k0 + i) * N + n0 + tx];
    __syncthreads();
    uint32_t* dst = (uint32_t*)(dstb + (long long)blockIdx.z * (long long)N * K);
    int tid = ty * 32 + tx;
    #pragma unroll
    for (int it = 0; it < 2; it++) {
        int j = tid + it * 256;          // 512 output u32 per tile
        int i = j >> 4, q = j & 15;      // n-row, u32-in-chunk
        int o = (q & 3) * 4 + (q >> 2);
        __half2 h = __floats2half2_rn(tile[2 * o][i], tile[2 * o + 1][i]);
        dst[(long long)(n0 + i) * (K / 2) + (k0 >> 1) + q] = h2u(h);
    }
}

// ---------------- fp16 mma.sync GEMM ----------------
// G1: g_h(packed f16) = relu(xh[g_tok] @ W1h + b1)   KTOT=512,  NTOT=2048
// G2: g_y = (g_h @ W2h + b2) * g_w                   KTOT=2048, NTOT=512
template <int KTOT, bool G1>
__global__ void __launch_bounds__(256) k_gemm(const float* __restrict__ bias)
{
    constexpr int NTOT = G1 ? HID : DIM;
    constexpr int CH = KTOT / BKH;

    extern __shared__ __align__(16) char smem[];

    int e = blockIdx.z;
    int seg0 = g_offsets[e], seg1 = g_offsets[e + 1];
    int m0 = seg0 + blockIdx.y * BM;
    if (m0 >= seg1) return;
    int n0 = blockIdx.x * BN;

    const __half* Asrc = G1 ? (const __half*)g_xh : (const __half*)g_h;
    const __half* W    = G1 ? (const __half*)g_W1h : (const __half*)g_W2h;

    int tid = threadIdx.x;
    int lane = tid & 31, wid = tid >> 5;
    int warp_m = wid & 1, warp_n = wid >> 1;

    // ---- cp.async mapping: pieces of 16B; row stride 64B; XOR-16B swizzle by row&3 ----
    int pr = tid >> 2;                   // base row 0..63
    int pc = tid & 3;                    // 16B piece in row
    uint32_t swz = (uint32_t)((pc ^ (pr & 3)) * 16);
    uint32_t sbase = smem_u32(smem);

    const __half* aP[2];
    uint32_t aD[2];
    #pragma unroll
    for (int i = 0; i < 2; i++) {
        int r = pr + i * 64;
        int gm = min(m0 + r, seg1 - 1);
        long long srow = G1 ? (long long)g_tok[gm] : (long long)gm;
        aP[i] = Asrc + srow * KTOT + pc * 8;
        aD[i] = sbase + (uint32_t)r * 64u + swz;
    }
    const __half* bP[4];
    uint32_t bD[4];
    #pragma unroll
    for (int k = 0; k < 4; k++) {
        int r = pr + k * 64;
        bP[k] = W + ((long long)e * NTOT + (n0 + r)) * (long long)KTOT + pc * 8;
        bD[k] = sbase + (uint32_t)A_BYTES + (uint32_t)r * 64u + swz;
    }

    auto load_chunk = [&](int c, int s) {
        uint32_t so = (uint32_t)(s * STAGE_BYTES);
        cp16(aD[0] + so, aP[0] + c * BKH);
        cp16(aD[1] + so, aP[1] + c * BKH);
        #pragma unroll
        for (int k = 0; k < 4; k++) cp16(bD[k] + so, bP[k] + c * BKH);
        asm volatile("cp.async.commit_group;" ::: "memory");
    };

    float acc[4][8][4];
    #pragma unroll
    for (int mi = 0; mi < 4; mi++)
        #pragma unroll
        for (int nj = 0; nj < 8; nj++)
            #pragma unroll
            for (int q = 0; q < 4; q++) acc[mi][nj][q] = 0.0f;

    load_chunk(0, 0);
    load_chunk(1, 1);

    // fragment byte offsets: row&3 == (lane>>2)&3 for all rows a warp touches
    uint32_t fswz = (uint32_t)(((lane & 3) ^ ((lane >> 2) & 3)) * 16);
    uint32_t aOff = (uint32_t)((warp_m * 64 + (lane >> 2)) * 64) + fswz;
    uint32_t bOff = (uint32_t)A_BYTES + (uint32_t)((warp_n * 64 + (lane >> 2)) * 64) + fswz;

    for (int c = 0; c < CH; c++) {
        int s = c % STAGES;
        if (c + 1 < CH) asm volatile("cp.async.wait_group 1;" ::: "memory");
        else            asm volatile("cp.async.wait_group 0;" ::: "memory");
        __syncthreads();

        const char* st = smem + s * STAGE_BYTES;

        uint4 aR[8];
        #pragma unroll
        for (int mi = 0; mi < 4; mi++) {
            aR[mi * 2 + 0] = *(const uint4*)(st + aOff + mi * 1024);
            aR[mi * 2 + 1] = *(const uint4*)(st + aOff + mi * 1024 + 512);
        }
        #pragma unroll
        for (int nj = 0; nj < 8; nj++) {
            uint4 b = *(const uint4*)(st + bOff + nj * 512);
            #pragma unroll
            for (int mi = 0; mi < 4; mi++) {
                mma16816(acc[mi][nj],
                         aR[mi * 2].x, aR[mi * 2 + 1].x, aR[mi * 2].y, aR[mi * 2 + 1].y,
                         b.x, b.y);
                mma16816(acc[mi][nj],
                         aR[mi * 2].z, aR[mi * 2 + 1].z, aR[mi * 2].w, aR[mi * 2 + 1].w,
                         b.z, b.w);
            }
        }

        __syncthreads();
        if (c + 2 < CH) load_chunk(c + 2, (c + 2) % STAGES);
    }

    // ---- epilogue ----
    const float* bias_e = bias + (long long)e * NTOT;
    float2 bv[8];
    #pragma unroll
    for (int nj = 0; nj < 8; nj++) {
        int col = n0 + warp_n * 64 + nj * 8 + (lane & 3) * 2;
        bv[nj] = *(const float2*)(bias_e + col);
    }

    if (G1) {
        // stage packed half2 into smem, then coalesced uint4 copy to g_h
        uint32_t* stg = (uint32_t*)smem;   // [128][132] u32
        #pragma unroll
        for (int mi = 0; mi < 4; mi++) {
            int r0 = warp_m * 64 + mi * 16 + (lane >> 2);   // block-relative row
            #pragma unroll
            for (int nj = 0; nj < 8; nj++) {
                // packed u32 position for cols (wc, wc+1), wc = warp_n*64+nj*8+2*(lane&3)
                int pos = (warp_n * 2 + (nj >> 2)) * 16 + 4 * (lane & 3) + (nj & 3);
                __half2 h0 = __floats2half2_rn(fmaxf(acc[mi][nj][0] + bv[nj].x, 0.0f),
                                               fmaxf(acc[mi][nj][1] + bv[nj].y, 0.0f));
                __half2 h1 = __floats2half2_rn(fmaxf(acc[mi][nj][2] + bv[nj].x, 0.0f),
                                               fmaxf(acc[mi][nj][3] + bv[nj].y, 0.0f));
                stg[r0 * 132 + pos]       = h2u(h0);
                stg[(r0 + 8) * 132 + pos] = h2u(h1);
            }
        }
        __syncthreads();
        uint32_t* gh = (uint32_t*)g_h;
        #pragma unroll
        for (int it = 0; it < 16; it++) {
            int j = tid + it * 256;            // 4096 uint4 total
            int row = j >> 5, q = j & 31;      // 128 rows x 32 uint4
            if (m0 + row < seg1) {
                uint4 v = *(const uint4*)(stg + row * 132 + q * 4);
                *(uint4*)(gh + (long long)(m0 + row) * (HID / 2) + (n0 >> 1) + q * 4) = v;
            }
        }
    } else {
        #pragma unroll
        for (int mi = 0; mi < 4; mi++) {
            int r0 = m0 + warp_m * 64 + mi * 16 + (lane >> 2);
            int r1 = r0 + 8;
            bool ok0 = r0 < seg1, ok1 = r1 < seg1;
            float w0 = ok0 ? g_w[r0] : 0.0f;
            float w1 = ok1 ? g_w[r1] : 0.0f;
            float* d0 = g_y + (long long)r0 * DIM;
            float* d1 = g_y + (long long)r1 * DIM;
            #pragma unroll
            for (int nj = 0; nj < 8; nj++) {
                int col = n0 + warp_n * 64 + nj * 8 + (lane & 3) * 2;
                float2 v0, v1;
                v0.x = (acc[mi][nj][0] + bv[nj].x) * w0;
                v0.y = (acc[mi][nj][1] + bv[nj].y) * w0;
                v1.x = (acc[mi][nj][2] + bv[nj].x) * w1;
                v1.y = (acc[mi][nj][3] + bv[nj].y) * w1;
                if (ok0) *(float2*)(d0 + col) = v0;
                if (ok1) *(float2*)(d1 + col) = v1;
            }
        }
    }
}

// ---------------- per-token gather ----------------
__global__ void k_gather(float* __restrict__ out) {
    int t = blockIdx.x;
    int c = threadIdx.x;   // 128 threads * float4 = 512 floats
    int cnt = g_cnt[t];
    int p0 = g_pos[2 * t];
    float4 v = ((const float4*)(g_y + (long long)p0 * DIM))[c];
    if (cnt == 2) {
        int p1 = g_pos[2 * t + 1];
        float4 u = ((const float4*)(g_y + (long long)p1 * DIM))[c];
        v.x += u.x; v.y += u.y; v.z += u.z; v.w += u.w;
    }
    ((float4*)(out + (long long)t * DIM))[c] = v;
}

// ---------------- launch ----------------
extern "C" void kernel_launch(void* const* d_in, const int* in_sizes, int n_in,
                              void* d_out, int out_size)
{
    const float* x      = (const float*)d_in[0];
    const int*   assign = (const int*)d_in[1];
    const float* W1     = (const float*)d_in[2];
    const float* b1     = (const float*)d_in[3];
    const float* W2     = (const float*)d_in[4];
    const float* b2     = (const float*)d_in[5];
    float* out = (float*)d_out;

    cudaFuncSetAttribute(k_gemm<DIM, true>,  cudaFuncAttributeMaxDynamicSharedMemorySize, SMEM_BYTES);
    cudaFuncSetAttribute(k_gemm<HID, false>, cudaFuncAttributeMaxDynamicSharedMemorySize, SMEM_BYTES);

    // pre-pack to fp16, k-fragment packed; W transposed to [n][k]
    k_pack_x<<<NTOK, 256>>>(x);
    dim3 tb(32, 8);
    k_pack_w<true ><<<dim3(HID / 32, DIM / 32, NEXP), tb>>>(W1, DIM, HID);
    k_pack_w<false><<<dim3(DIM / 32, HID / 32, NEXP), tb>>>(W2, HID, DIM);

    // routing
    k_zero<<<1, 32>>>();
    k_count<<<NTOK / 256, 256>>>(assign);
    k_scan<<<1, 1>>>();
    k_place<<<NTOK / 256, 256>>>(assign);

    // GEMM1: entries x 512 @ 512 x 2048 -> g_h (fp16 packed)
    dim3 g1(HID / BN, MAXE / BM, NEXP);   // (8, 512, 8)
    k_gemm<DIM, true><<<g1, 256, SMEM_BYTES>>>(b1);

    // GEMM2: entries x 2048 @ 2048 x 512 -> g_y
    dim3 g2(DIM / BN, MAXE / BM, NEXP);   // (2, 512, 8)
    k_gemm<HID, false><<<g2, 256, SMEM_BYTES>>>(b2);

    k_gather<<<NTOK, 128>>>(out);
}